// round 6
// baseline (speedup 1.0000x reference)
#include <cuda_runtime.h>
#include <math.h>

// Problem constants (fixed shapes per reference)
#define NN    10000
#define INC   128
#define H1C   8
#define C1C   128
#define D1    1024      // H1C*C1C
#define OUTC  64
#define MAXE  200000
#define MAXEE (MAXE + NN)

// ---------------- device scratch (no allocations allowed) ----------------
__device__ int   g_src[MAXEE];
__device__ int   g_dst[MAXEE];
__device__ int   g_esrc[MAXEE];     // CSR: src per dst-sorted edge
__device__ int   g_rowptr[NN + 1];
__device__ int   g_cursor[NN];
__device__ int   g_deg[NN];
__device__ float g_h1[NN * D1];     // gemm1 output
__device__ float g_act[NN * D1];    // layer-1 elu output (layer-2 input)
__device__ float g_as1[NN * H1C];
__device__ float g_ad1[NN * H1C];
__device__ float g_z[NN * OUTC];
__device__ float g_as2[NN];
__device__ float g_ad2[NN];
__device__ int   g_is64;

// ---------------- prep: zero degree array; block 0 also detects edge dtype ----------------
// If edge_index is int64 (values < 2^31), every odd 32-bit word is zero.
__global__ void k_prep(const int* __restrict__ ei, int E) {
    int i = blockIdx.x * blockDim.x + threadIdx.x;
    if (i < NN) g_deg[i] = 0;
    if (blockIdx.x == 0) {
        __shared__ int nz;
        if (threadIdx.x == 0) nz = 0;
        __syncthreads();
        int n = E < 1000 ? E : 1000;
        int local = 0;
        for (int j = threadIdx.x; j < n; j += blockDim.x)
            if (ei[2 * j + 1] != 0) local = 1;
        if (local) atomicOr(&nz, 1);
        __syncthreads();
        if (threadIdx.x == 0) g_is64 = (nz == 0) ? 1 : 0;
    }
}

// Build int32 src/dst with self-loops appended + histogram of dst degrees.
__global__ void k_build_hist(const void* __restrict__ ei, int E, int total) {
    int i = blockIdx.x * blockDim.x + threadIdx.x;
    if (i >= total) return;
    int s, d;
    if (i < E) {
        if (g_is64) {
            const long long* p = (const long long*)ei;
            s = (int)p[i];
            d = (int)p[E + i];
        } else {
            const int* p = (const int*)ei;
            s = p[i];
            d = p[E + i];
        }
    } else {
        s = i - E;
        d = i - E;
    }
    g_src[i] = s;
    g_dst[i] = d;
    atomicAdd(&g_deg[d], 1);
}

// Exclusive scan of g_deg -> g_rowptr (and init g_cursor). Single block, 1024 threads.
__global__ void k_scan() {
    __shared__ int sums[1024];
    const int CH = (NN + 1023) / 1024;   // 10
    int tid = threadIdx.x;
    int base = tid * CH;
    int s = 0;
    for (int j = 0; j < CH; j++) {
        int idx = base + j;
        if (idx < NN) s += g_deg[idx];
    }
    sums[tid] = s;
    __syncthreads();
    for (int off = 1; off < 1024; off <<= 1) {
        int v = (tid >= off) ? sums[tid - off] : 0;
        __syncthreads();
        sums[tid] += v;
        __syncthreads();
    }
    int run = (tid == 0) ? 0 : sums[tid - 1];
    for (int j = 0; j < CH; j++) {
        int idx = base + j;
        if (idx < NN) {
            g_rowptr[idx] = run;
            g_cursor[idx] = run;
            run += g_deg[idx];
        }
    }
    if (tid == 1023) g_rowptr[NN] = run;
}

__global__ void k_scatter(int EE) {
    int i = blockIdx.x * blockDim.x + threadIdx.x;
    if (i >= EE) return;
    int p = atomicAdd(&g_cursor[g_dst[i]], 1);
    g_esrc[p] = g_src[i];
}

// ---------------- GEMM1: g_h1 = x @ W1, 128x128 tile, BK=16, 8x8/thread ----------------
// Fused epilogue: per-head alpha_src/alpha_dst reductions (tile N-dim == one head).
__global__ void __launch_bounds__(256) k_gemm1(const float* __restrict__ A,
                                               const float* __restrict__ B,
                                               const float* __restrict__ asrc,
                                               const float* __restrict__ adst) {
    __shared__ float As[2][16][132];
    __shared__ float Bs[2][16][132];
    const int M = NN, N = D1, K = INC;
    int tid = threadIdx.x;
    int row0 = blockIdx.y * 128, col0 = blockIdx.x * 128;
    int tx = tid & 15, ty = tid >> 4;
    float acc[8][8] = {};

    // stage 0 load
    {
#pragma unroll
        for (int i = 0; i < 2; i++) {
            int idx = tid + i * 256;
            int m = idx >> 2, kq = (idx & 3) * 4;
            int gm = row0 + m;
            float4 v = make_float4(0.f, 0.f, 0.f, 0.f);
            if (gm < M) v = *(const float4*)&A[(size_t)gm * K + kq];
            As[0][kq + 0][m] = v.x; As[0][kq + 1][m] = v.y;
            As[0][kq + 2][m] = v.z; As[0][kq + 3][m] = v.w;
        }
#pragma unroll
        for (int i = 0; i < 2; i++) {
            int idx = tid + i * 256;
            int k2 = idx >> 5, n4 = (idx & 31) * 4;
            float4 v = *(const float4*)&B[(size_t)k2 * N + col0 + n4];
            *(float4*)&Bs[0][k2][n4] = v;
        }
    }
    __syncthreads();

    int buf = 0;
    const int NSTAGE = K / 16;   // 8
    for (int it = 1; it <= NSTAGE; it++) {
        float4 pa[2], pb[2];
        if (it < NSTAGE) {
            int k0 = it * 16;
#pragma unroll
            for (int i = 0; i < 2; i++) {
                int idx = tid + i * 256;
                int m = idx >> 2, kq = (idx & 3) * 4;
                int gm = row0 + m;
                pa[i] = make_float4(0.f, 0.f, 0.f, 0.f);
                if (gm < M) pa[i] = *(const float4*)&A[(size_t)gm * K + k0 + kq];
            }
#pragma unroll
            for (int i = 0; i < 2; i++) {
                int idx = tid + i * 256;
                int k2 = idx >> 5, n4 = (idx & 31) * 4;
                pb[i] = *(const float4*)&B[(size_t)(k0 + k2) * N + col0 + n4];
            }
        }
#pragma unroll
        for (int kk = 0; kk < 16; kk++) {
            float4 a0 = *(float4*)&As[buf][kk][ty * 8];
            float4 a1 = *(float4*)&As[buf][kk][ty * 8 + 4];
            float4 b0 = *(float4*)&Bs[buf][kk][tx * 8];
            float4 b1 = *(float4*)&Bs[buf][kk][tx * 8 + 4];
            float av[8] = {a0.x, a0.y, a0.z, a0.w, a1.x, a1.y, a1.z, a1.w};
            float bv[8] = {b0.x, b0.y, b0.z, b0.w, b1.x, b1.y, b1.z, b1.w};
#pragma unroll
            for (int i = 0; i < 8; i++)
#pragma unroll
                for (int j = 0; j < 8; j++) acc[i][j] += av[i] * bv[j];
        }
        if (it < NSTAGE) {
            int nb = buf ^ 1;
#pragma unroll
            for (int i = 0; i < 2; i++) {
                int idx = tid + i * 256;
                int m = idx >> 2, kq = (idx & 3) * 4;
                As[nb][kq + 0][m] = pa[i].x; As[nb][kq + 1][m] = pa[i].y;
                As[nb][kq + 2][m] = pa[i].z; As[nb][kq + 3][m] = pa[i].w;
            }
#pragma unroll
            for (int i = 0; i < 2; i++) {
                int idx = tid + i * 256;
                int k2 = idx >> 5, n4 = (idx & 31) * 4;
                *(float4*)&Bs[nb][k2][n4] = pb[i];
            }
            __syncthreads();
            buf = nb;
        }
    }

    // store C
#pragma unroll
    for (int i = 0; i < 8; i++) {
        int gm = row0 + ty * 8 + i;
        if (gm < M) {
            *(float4*)&g_h1[(size_t)gm * N + col0 + tx * 8] =
                make_float4(acc[i][0], acc[i][1], acc[i][2], acc[i][3]);
            *(float4*)&g_h1[(size_t)gm * N + col0 + tx * 8 + 4] =
                make_float4(acc[i][4], acc[i][5], acc[i][6], acc[i][7]);
        }
    }

    // fused alpha: this tile's 128 cols == head h = blockIdx.x
    int h = blockIdx.x;
    float avs[8], avd[8];
#pragma unroll
    for (int j = 0; j < 8; j++) {
        avs[j] = asrc[h * C1C + tx * 8 + j];
        avd[j] = adst[h * C1C + tx * 8 + j];
    }
#pragma unroll
    for (int i = 0; i < 8; i++) {
        float s = 0.f, d = 0.f;
#pragma unroll
        for (int j = 0; j < 8; j++) {
            s += acc[i][j] * avs[j];
            d += acc[i][j] * avd[j];
        }
        // reduce over tx (16 lanes per segment)
#pragma unroll
        for (int o = 8; o; o >>= 1) {
            s += __shfl_down_sync(0xffffffffu, s, o, 16);
            d += __shfl_down_sync(0xffffffffu, d, o, 16);
        }
        int gm = row0 + ty * 8 + i;
        if (tx == 0 && gm < M) {
            g_as1[gm * H1C + h] = s;
            g_ad1[gm * H1C + h] = d;
        }
    }
}

// ---------------- GEMM2: g_z = g_act @ W2, 64x64 tile, BK=16, 4x4/thread ----------------
// Fused epilogue: layer-2 alpha reductions (tile covers all OUTC cols).
__global__ void __launch_bounds__(256) k_gemm2(const float* __restrict__ B,
                                               const float* __restrict__ a2s,
                                               const float* __restrict__ a2d) {
    __shared__ float As[2][16][68];
    __shared__ float Bs[2][16][68];
    const int M = NN, N = OUTC, K = D1;
    const float* A = g_act;
    int tid = threadIdx.x;
    int row0 = blockIdx.x * 64;
    int tx = tid & 15, ty = tid >> 4;
    float acc[4][4] = {};

    // stage 0
    {
        int m = tid >> 2, kq = (tid & 3) * 4;
        int gm = row0 + m;
        float4 v = make_float4(0.f, 0.f, 0.f, 0.f);
        if (gm < M) v = *(const float4*)&A[(size_t)gm * K + kq];
        As[0][kq + 0][m] = v.x; As[0][kq + 1][m] = v.y;
        As[0][kq + 2][m] = v.z; As[0][kq + 3][m] = v.w;
        int k2 = tid >> 4, n4 = (tid & 15) * 4;
        *(float4*)&Bs[0][k2][n4] = *(const float4*)&B[(size_t)k2 * N + n4];
    }
    __syncthreads();

    int buf = 0;
    const int NSTAGE = K / 16;   // 64
    for (int it = 1; it <= NSTAGE; it++) {
        float4 pa, pb;
        if (it < NSTAGE) {
            int k0 = it * 16;
            int m = tid >> 2, kq = (tid & 3) * 4;
            int gm = row0 + m;
            pa = make_float4(0.f, 0.f, 0.f, 0.f);
            if (gm < M) pa = *(const float4*)&A[(size_t)gm * K + k0 + kq];
            int k2 = tid >> 4, n4 = (tid & 15) * 4;
            pb = *(const float4*)&B[(size_t)(k0 + k2) * N + n4];
        }
#pragma unroll
        for (int kk = 0; kk < 16; kk++) {
            float4 a = *(float4*)&As[buf][kk][ty * 4];
            float4 b = *(float4*)&Bs[buf][kk][tx * 4];
            float av[4] = {a.x, a.y, a.z, a.w};
            float bv[4] = {b.x, b.y, b.z, b.w};
#pragma unroll
            for (int i = 0; i < 4; i++)
#pragma unroll
                for (int j = 0; j < 4; j++) acc[i][j] += av[i] * bv[j];
        }
        if (it < NSTAGE) {
            int nb = buf ^ 1;
            int m = tid >> 2, kq = (tid & 3) * 4;
            As[nb][kq + 0][m] = pa.x; As[nb][kq + 1][m] = pa.y;
            As[nb][kq + 2][m] = pa.z; As[nb][kq + 3][m] = pa.w;
            int k2 = tid >> 4, n4 = (tid & 15) * 4;
            *(float4*)&Bs[nb][k2][n4] = pb;
            __syncthreads();
            buf = nb;
        }
    }

#pragma unroll
    for (int i = 0; i < 4; i++) {
        int gm = row0 + ty * 4 + i;
        if (gm < M)
            *(float4*)&g_z[(size_t)gm * N + tx * 4] =
                make_float4(acc[i][0], acc[i][1], acc[i][2], acc[i][3]);
    }

    // fused alpha2 (cols 0..63 all in-tile)
    float avs[4], avd[4];
#pragma unroll
    for (int j = 0; j < 4; j++) {
        avs[j] = a2s[tx * 4 + j];
        avd[j] = a2d[tx * 4 + j];
    }
#pragma unroll
    for (int i = 0; i < 4; i++) {
        float s = 0.f, d = 0.f;
#pragma unroll
        for (int j = 0; j < 4; j++) {
            s += acc[i][j] * avs[j];
            d += acc[i][j] * avd[j];
        }
#pragma unroll
        for (int o = 8; o; o >>= 1) {
            s += __shfl_down_sync(0xffffffffu, s, o, 16);
            d += __shfl_down_sync(0xffffffffu, d, o, 16);
        }
        int gm = row0 + ty * 4 + i;
        if (tx == 0 && gm < M) {
            g_as2[gm] = s;
            g_ad2[gm] = d;
        }
    }
}

// ---------------- CSR edge pass 1: one block per dst node, fused softmax+agg+elu ----------------
// 128 threads: thread t owns head h=t>>4, channels h*128 + (t&15)*8 .. +8.
// No max-subtraction needed: self-loop guarantees den >= exp(e_self); |e| is O(5).
__global__ void k_edge1(const float* __restrict__ b1) {
    int n = blockIdx.x;
    int tid = threadIdx.x;
    int h = tid >> 4;
    int c0 = h * C1C + (tid & 15) * 8;
    float ad = g_ad1[n * H1C + h];
    float acc[8] = {};
    float den = 0.f;
    int e0 = g_rowptr[n], e1 = g_rowptr[n + 1];
    int srcLane = threadIdx.x & 16;   // lane 0 or 16 within warp owns the expf
    for (int e = e0; e < e1; e++) {
        int s = g_esrc[e];
        float w = 0.f;
        if ((tid & 15) == 0) {
            float ev = g_as1[s * H1C + h] + ad;
            ev = ev > 0.f ? ev : 0.2f * ev;
            w = __expf(ev);
        }
        w = __shfl_sync(0xffffffffu, w, srcLane, 32);
        den += w;
        const float4* hp = (const float4*)(g_h1 + (size_t)s * D1 + c0);
        float4 p = hp[0], q = hp[1];
        acc[0] += w * p.x; acc[1] += w * p.y; acc[2] += w * p.z; acc[3] += w * p.w;
        acc[4] += w * q.x; acc[5] += w * q.y; acc[6] += w * q.z; acc[7] += w * q.w;
    }
    float inv = 1.f / (den + 1e-16f);
    float* op = g_act + (size_t)n * D1 + c0;
    float4 r0, r1;
    float v;
    v = acc[0] * inv + b1[c0 + 0]; r0.x = v > 0.f ? v : expm1f(v);
    v = acc[1] * inv + b1[c0 + 1]; r0.y = v > 0.f ? v : expm1f(v);
    v = acc[2] * inv + b1[c0 + 2]; r0.z = v > 0.f ? v : expm1f(v);
    v = acc[3] * inv + b1[c0 + 3]; r0.w = v > 0.f ? v : expm1f(v);
    v = acc[4] * inv + b1[c0 + 4]; r1.x = v > 0.f ? v : expm1f(v);
    v = acc[5] * inv + b1[c0 + 5]; r1.y = v > 0.f ? v : expm1f(v);
    v = acc[6] * inv + b1[c0 + 6]; r1.z = v > 0.f ? v : expm1f(v);
    v = acc[7] * inv + b1[c0 + 7]; r1.w = v > 0.f ? v : expm1f(v);
    ((float4*)op)[0] = r0;
    ((float4*)op)[1] = r1;
}

// ---------------- CSR edge pass 2: warp per dst node, fused final output ----------------
__global__ void k_edge2(float* __restrict__ out, const float* __restrict__ b2) {
    int n = (blockIdx.x * blockDim.x + threadIdx.x) >> 5;
    int lane = threadIdx.x & 31;
    if (n >= NN) return;
    float ad = g_ad2[n];
    float acc0 = 0.f, acc1 = 0.f, den = 0.f;
    int e0 = g_rowptr[n], e1 = g_rowptr[n + 1];
    for (int e = e0; e < e1; e++) {
        int s = g_esrc[e];
        float w = 0.f;
        if (lane == 0) {
            float ev = g_as2[s] + ad;
            ev = ev > 0.f ? ev : 0.2f * ev;
            w = __expf(ev);
        }
        w = __shfl_sync(0xffffffffu, w, 0, 32);
        den += w;
        const float* zs = g_z + (size_t)s * OUTC;
        acc0 += w * zs[lane];
        acc1 += w * zs[lane + 32];
    }
    float inv = 1.f / (den + 1e-16f);
    out[(size_t)n * OUTC + lane]      = acc0 * inv + b2[lane];
    out[(size_t)n * OUTC + lane + 32] = acc1 * inv + b2[lane + 32];
}

// ---------------- host launcher ----------------
extern "C" void kernel_launch(void* const* d_in, const int* in_sizes, int n_in,
                              void* d_out, int out_size) {
    const float* x    = (const float*)d_in[0];
    const void*  ei   = d_in[1];
    const float* W1   = (const float*)d_in[2];
    const float* a_s1 = (const float*)d_in[3];
    const float* a_d1 = (const float*)d_in[4];
    const float* b1   = (const float*)d_in[5];
    const float* W2   = (const float*)d_in[6];
    const float* a_s2 = (const float*)d_in[7];
    const float* a_d2 = (const float*)d_in[8];
    const float* b2   = (const float*)d_in[9];
    float* out = (float*)d_out;

    int E = in_sizes[1] / 2;
    if (E > MAXE) E = MAXE;
    int EE = E + NN;

    // CSR build
    k_prep<<<(NN + 255) / 256, 256>>>((const int*)ei, E);
    k_build_hist<<<(EE + 255) / 256, 256>>>(ei, E, EE);
    k_scan<<<1, 1024>>>();
    k_scatter<<<(EE + 255) / 256, 256>>>(EE);

    // layer 1
    k_gemm1<<<dim3(D1 / 128, (NN + 127) / 128), 256>>>(x, W1, a_s1, a_d1);
    k_edge1<<<NN, 128>>>(b1);

    // layer 2
    k_gemm2<<<(NN + 63) / 64, 256>>>(W2, a_s2, a_d2);
    k_edge2<<<(NN * 32 + 255) / 256, 256>>>(out, b2);
}

// round 13
// speedup vs baseline: 1.2193x; 1.2193x over previous
#include <cuda_runtime.h>
#include <cuda_bf16.h>
#include <cstdint>
#include <math.h>

// Problem constants (fixed shapes per reference)
#define NN    10000
#define INC   128
#define H1C   8
#define C1C   128
#define D1    1024      // H1C*C1C
#define OUTC  64
#define MAXE  200000
#define MAXEE (MAXE + NN)

// ---------------- warp-level MMA helpers (baseline sm_80+ ISA; no 'a' features) ----------------
__device__ __forceinline__ uint32_t smem_to_u32(const void* p) {
    uint32_t a;
    asm("{ .reg .u64 t; cvta.to.shared.u64 t, %1; cvt.u32.u64 %0, t; }" : "=r"(a) : "l"(p));
    return a;
}
__device__ __forceinline__ void ldmx4(uint32_t addr, uint32_t& r0, uint32_t& r1,
                                      uint32_t& r2, uint32_t& r3) {
    asm volatile("ldmatrix.sync.aligned.m8n8.x4.shared.b16 {%0,%1,%2,%3}, [%4];"
        : "=r"(r0), "=r"(r1), "=r"(r2), "=r"(r3) : "r"(addr));
}
__device__ __forceinline__ void mma16816(float* c, const uint32_t* a, const uint32_t* b) {
    asm volatile("mma.sync.aligned.m16n8k16.row.col.f32.bf16.bf16.f32 "
        "{%0,%1,%2,%3}, {%4,%5,%6,%7}, {%8,%9}, {%0,%1,%2,%3};"
        : "+f"(c[0]), "+f"(c[1]), "+f"(c[2]), "+f"(c[3])
        : "r"(a[0]), "r"(a[1]), "r"(a[2]), "r"(a[3]), "r"(b[0]), "r"(b[1]));
}

// ---------------- device scratch (no allocations allowed) ----------------
__device__ int   g_src[MAXEE];
__device__ int   g_dst[MAXEE];
__device__ int   g_esrc[MAXEE];     // CSR: src per dst-sorted edge
__device__ int   g_rowptr[NN + 1];
__device__ int   g_cursor[NN];
__device__ int   g_deg[NN];
__device__ float g_h1[NN * D1];     // gemm1 output (fp32)
__device__ float g_as1[NN * H1C];
__device__ float g_ad1[NN * H1C];
__device__ float g_z[NN * OUTC];
__device__ float g_as2[NN];
__device__ float g_ad2[NN];
__device__ int   g_is64;
// split-bf16 operands
__device__ __nv_bfloat16 g_xh[NN * INC];
__device__ __nv_bfloat16 g_xl[NN * INC];
__device__ __nv_bfloat16 g_w1th[D1 * INC];   // W1^T hi  [n][k]
__device__ __nv_bfloat16 g_w1tl[D1 * INC];   // W1^T lo
__device__ __nv_bfloat16 g_w2th[OUTC * D1];  // W2^T hi
__device__ __nv_bfloat16 g_w2tl[OUTC * D1];  // W2^T lo
__device__ __nv_bfloat16 g_acth[NN * D1];    // layer-1 activation hi
__device__ __nv_bfloat16 g_actl[NN * D1];    // layer-1 activation lo

// ---------------- prep: zero degree array; block 0 also detects edge dtype ----------------
__global__ void k_prep(const int* __restrict__ ei, int E) {
    int i = blockIdx.x * blockDim.x + threadIdx.x;
    if (i < NN) g_deg[i] = 0;
    if (blockIdx.x == 0) {
        __shared__ int nz;
        if (threadIdx.x == 0) nz = 0;
        __syncthreads();
        int n = E < 1000 ? E : 1000;
        int local = 0;
        for (int j = threadIdx.x; j < n; j += blockDim.x)
            if (ei[2 * j + 1] != 0) local = 1;
        if (local) atomicOr(&nz, 1);
        __syncthreads();
        if (threadIdx.x == 0) g_is64 = (nz == 0) ? 1 : 0;
    }
}

// Build int32 src/dst with self-loops appended + histogram of dst degrees.
__global__ void k_build_hist(const void* __restrict__ ei, int E, int total) {
    int i = blockIdx.x * blockDim.x + threadIdx.x;
    if (i >= total) return;
    int s, d;
    if (i < E) {
        if (g_is64) {
            const long long* p = (const long long*)ei;
            s = (int)p[i];
            d = (int)p[E + i];
        } else {
            const int* p = (const int*)ei;
            s = p[i];
            d = p[E + i];
        }
    } else {
        s = i - E;
        d = i - E;
    }
    // clamp defensively (malformed indices would otherwise fault downstream)
    s = s < 0 ? 0 : (s >= NN ? NN - 1 : s);
    d = d < 0 ? 0 : (d >= NN ? NN - 1 : d);
    g_src[i] = s;
    g_dst[i] = d;
    atomicAdd(&g_deg[d], 1);
}

// Exclusive scan of g_deg -> g_rowptr (and init g_cursor). Single block, 1024 threads.
__global__ void k_scan() {
    __shared__ int sums[1024];
    const int CH = (NN + 1023) / 1024;   // 10
    int tid = threadIdx.x;
    int base = tid * CH;
    int s = 0;
    for (int j = 0; j < CH; j++) {
        int idx = base + j;
        if (idx < NN) s += g_deg[idx];
    }
    sums[tid] = s;
    __syncthreads();
    for (int off = 1; off < 1024; off <<= 1) {
        int v = (tid >= off) ? sums[tid - off] : 0;
        __syncthreads();
        sums[tid] += v;
        __syncthreads();
    }
    int run = (tid == 0) ? 0 : sums[tid - 1];
    for (int j = 0; j < CH; j++) {
        int idx = base + j;
        if (idx < NN) {
            g_rowptr[idx] = run;
            g_cursor[idx] = run;
            run += g_deg[idx];
        }
    }
    if (tid == 1023) g_rowptr[NN] = run;
}

__global__ void k_scatter(int EE) {
    int i = blockIdx.x * blockDim.x + threadIdx.x;
    if (i >= EE) return;
    int p = atomicAdd(&g_cursor[g_dst[i]], 1);
    g_esrc[p] = g_src[i];
}

// ---------------- split-bf16 conversion: x, W1^T, W2^T ----------------
__global__ void k_cvt(const float* __restrict__ x, const float* __restrict__ W1,
                      const float* __restrict__ W2) {
    const int NX = NN * INC;           // 1,280,000
    const int NW1 = D1 * INC;          // 131,072
    const int NW2 = OUTC * D1;         // 65,536
    int i = blockIdx.x * blockDim.x + threadIdx.x;
    if (i < NX) {
        float v = x[i];
        __nv_bfloat16 h = __float2bfloat16(v);
        g_xh[i] = h;
        g_xl[i] = __float2bfloat16(v - __bfloat162float(h));
    } else if (i < NX + NW1) {
        int idx = i - NX;
        int n = idx >> 7, k = idx & 127;           // [n][k] <- W1[k][n]
        float v = W1[(size_t)k * D1 + n];
        __nv_bfloat16 h = __float2bfloat16(v);
        g_w1th[idx] = h;
        g_w1tl[idx] = __float2bfloat16(v - __bfloat162float(h));
    } else if (i < NX + NW1 + NW2) {
        int idx = i - NX - NW1;
        int n = idx >> 10, k = idx & 1023;         // [n][k] <- W2[k][n]
        float v = W2[(size_t)k * OUTC + n];
        __nv_bfloat16 h = __float2bfloat16(v);
        g_w2th[idx] = h;
        g_w2tl[idx] = __float2bfloat16(v - __bfloat162float(h));
    }
}

// smem row pitch: 72 bf16 = 144 bytes = 9 x 16B => ldmatrix conflict-free, no swizzle
#define PITCH 72

// ---------------- GEMM1 (HMMA): g_h1 = x @ W1 via concatenated-K split-bf16 ----------------
// K' = 384 (xh@Wh | xh@Wl | xl@Wh), 6 chunks of 64. CTA tile 128x128, 8 warps of 32x64.
__global__ void __launch_bounds__(256) k_gemm1() {
    __shared__ __align__(16) __nv_bfloat16 smA[128 * PITCH];
    __shared__ __align__(16) __nv_bfloat16 smB[128 * PITCH];
    int tid = threadIdx.x, wid = tid >> 5, lane = tid & 31;
    int row0 = blockIdx.y * 128, col0 = blockIdx.x * 128;
    int mw = (wid >> 1) * 32, nw = (wid & 1) * 64;
    float acc[2][8][4];
#pragma unroll
    for (int mi = 0; mi < 2; mi++)
#pragma unroll
        for (int ni = 0; ni < 8; ni++)
#pragma unroll
            for (int j = 0; j < 4; j++) acc[mi][ni][j] = 0.f;

    uint32_t smA32 = smem_to_u32(smA), smB32 = smem_to_u32(smB);
    // ldmatrix lane address bases (bytes)
    uint32_t aAddr = smA32 + (mw + (lane & 15)) * 144 + (lane >> 4) * 16;
    uint32_t bAddr = smB32 + (nw + (lane & 7) + ((lane >> 4) & 1) * 8) * 144 + ((lane >> 3) & 1) * 16;

    for (int ci = 0; ci < 6; ci++) {
        int t = ci >> 1, kin = (ci & 1) * 64;
        const __nv_bfloat16* Ag = (t < 2) ? g_xh : g_xl;
        const __nv_bfloat16* Bg = (t == 1) ? g_w1tl : g_w1th;
        // load A chunk: 128 rows x 64 bf16 (1024 uint4, 4/thread)
#pragma unroll
        for (int i = 0; i < 4; i++) {
            int u = tid + i * 256;
            int r = u >> 3, q = u & 7;
            int gm = row0 + r;
            uint4 v = make_uint4(0u, 0u, 0u, 0u);
            if (gm < NN) v = *(const uint4*)(Ag + (size_t)gm * INC + kin + q * 8);
            *(uint4*)(smA + r * PITCH + q * 8) = v;
        }
        // load B chunk: 128 n-rows x 64 bf16 (guarded)
#pragma unroll
        for (int i = 0; i < 4; i++) {
            int u = tid + i * 256;
            int r = u >> 3, q = u & 7;
            int gn = col0 + r;
            uint4 v = make_uint4(0u, 0u, 0u, 0u);
            if (gn < D1) v = *(const uint4*)(Bg + (size_t)gn * INC + kin + q * 8);
            *(uint4*)(smB + r * PITCH + q * 8) = v;
        }
        __syncthreads();
#pragma unroll
        for (int kk = 0; kk < 4; kk++) {
            uint32_t a[2][4], b[8][2];
            ldmx4(aAddr + kk * 32, a[0][0], a[0][1], a[0][2], a[0][3]);
            ldmx4(aAddr + 16 * 144 + kk * 32, a[1][0], a[1][1], a[1][2], a[1][3]);
#pragma unroll
            for (int nt = 0; nt < 4; nt++) {
                uint32_t r0, r1, r2, r3;
                ldmx4(bAddr + nt * 16 * 144 + kk * 32, r0, r1, r2, r3);
                b[nt * 2][0] = r0; b[nt * 2][1] = r1;
                b[nt * 2 + 1][0] = r2; b[nt * 2 + 1][1] = r3;
            }
#pragma unroll
            for (int mi = 0; mi < 2; mi++)
#pragma unroll
                for (int ni = 0; ni < 8; ni++)
                    mma16816(acc[mi][ni], a[mi], b[ni]);
        }
        __syncthreads();
    }
    // epilogue: write fp32 h1
    int rbase = row0 + mw + (lane >> 2);
    int cbase = col0 + nw + (lane & 3) * 2;
#pragma unroll
    for (int mi = 0; mi < 2; mi++)
#pragma unroll
        for (int ni = 0; ni < 8; ni++) {
            int r = rbase + mi * 16;
            int c = cbase + ni * 8;
            if (r < NN)
                *(float2*)(g_h1 + (size_t)r * D1 + c) = make_float2(acc[mi][ni][0], acc[mi][ni][1]);
            if (r + 8 < NN)
                *(float2*)(g_h1 + (size_t)(r + 8) * D1 + c) = make_float2(acc[mi][ni][2], acc[mi][ni][3]);
        }
}

// ---------------- GEMM2 (HMMA): g_z = act @ W2 via concatenated-K split-bf16 ----------------
// K' = 3072 (48 chunks of 64). CTA tile 128x64, 8 warps of 16x64.
__global__ void __launch_bounds__(256) k_gemm2() {
    __shared__ __align__(16) __nv_bfloat16 smA[128 * PITCH];
    __shared__ __align__(16) __nv_bfloat16 smB[64 * PITCH];
    int tid = threadIdx.x, wid = tid >> 5, lane = tid & 31;
    int row0 = blockIdx.x * 128;
    int mw = wid * 16;
    float acc[8][4];
#pragma unroll
    for (int ni = 0; ni < 8; ni++)
#pragma unroll
        for (int j = 0; j < 4; j++) acc[ni][j] = 0.f;

    uint32_t smA32 = smem_to_u32(smA), smB32 = smem_to_u32(smB);
    uint32_t aAddr = smA32 + (mw + (lane & 15)) * 144 + (lane >> 4) * 16;
    uint32_t bAddr = smB32 + ((lane & 7) + ((lane >> 4) & 1) * 8) * 144 + ((lane >> 3) & 1) * 16;

    for (int ci = 0; ci < 48; ci++) {
        int t = ci >> 4, kin = (ci & 15) * 64;
        const __nv_bfloat16* Ag = (t < 2) ? g_acth : g_actl;
        const __nv_bfloat16* Bg = (t == 1) ? g_w2tl : g_w2th;
#pragma unroll
        for (int i = 0; i < 4; i++) {
            int u = tid + i * 256;
            int r = u >> 3, q = u & 7;
            int gm = row0 + r;
            uint4 v = make_uint4(0u, 0u, 0u, 0u);
            if (gm < NN) v = *(const uint4*)(Ag + (size_t)gm * D1 + kin + q * 8);
            *(uint4*)(smA + r * PITCH + q * 8) = v;
        }
#pragma unroll
        for (int i = 0; i < 2; i++) {
            int u = tid + i * 256;
            int r = u >> 3, q = u & 7;
            uint4 v = *(const uint4*)(Bg + (size_t)r * D1 + kin + q * 8);
            *(uint4*)(smB + r * PITCH + q * 8) = v;
        }
        __syncthreads();
#pragma unroll
        for (int kk = 0; kk < 4; kk++) {
            uint32_t a[4], b[8][2];
            ldmx4(aAddr + kk * 32, a[0], a[1], a[2], a[3]);
#pragma unroll
            for (int nt = 0; nt < 4; nt++) {
                uint32_t r0, r1, r2, r3;
                ldmx4(bAddr + nt * 16 * 144 + kk * 32, r0, r1, r2, r3);
                b[nt * 2][0] = r0; b[nt * 2][1] = r1;
                b[nt * 2 + 1][0] = r2; b[nt * 2 + 1][1] = r3;
            }
#pragma unroll
            for (int ni = 0; ni < 8; ni++)
                mma16816(acc[ni], a, b[ni]);
        }
        __syncthreads();
    }
    int rbase = row0 + mw + (lane >> 2);
    int cbase = (lane & 3) * 2;
#pragma unroll
    for (int ni = 0; ni < 8; ni++) {
        int c = cbase + ni * 8;
        if (rbase < NN)
            *(float2*)(g_z + (size_t)rbase * OUTC + c) = make_float2(acc[ni][0], acc[ni][1]);
        if (rbase + 8 < NN)
            *(float2*)(g_z + (size_t)(rbase + 8) * OUTC + c) = make_float2(acc[ni][2], acc[ni][3]);
    }
}

// ---------------- layer-1 attention coefficients: warp per (node, head) ----------------
__global__ void k_alpha1(const float* __restrict__ asrc, const float* __restrict__ adst) {
    int w = (blockIdx.x * blockDim.x + threadIdx.x) >> 5;
    int lane = threadIdx.x & 31;
    if (w >= NN * H1C) return;
    int n = w >> 3, hh = w & 7;
    const float* hp = g_h1 + (size_t)n * D1 + hh * C1C;
    const float* ap = asrc + hh * C1C;
    const float* bp = adst + hh * C1C;
    float s = 0.f, d = 0.f;
#pragma unroll
    for (int j = 0; j < 4; j++) {
        float v = hp[lane + j * 32];
        s += v * ap[lane + j * 32];
        d += v * bp[lane + j * 32];
    }
    for (int o = 16; o; o >>= 1) {
        s += __shfl_down_sync(0xffffffffu, s, o);
        d += __shfl_down_sync(0xffffffffu, d, o);
    }
    if (lane == 0) { g_as1[w] = s; g_ad1[w] = d; }
}

// ---------------- CSR edge pass 1: block per dst node, fused softmax+agg+elu ----------------
// Output written directly as split-bf16 (hi/lo) for GEMM2.
__global__ void k_edge1(const float* __restrict__ b1) {
    int n = blockIdx.x;
    int tid = threadIdx.x;
    int h = tid >> 4;
    int c0 = h * C1C + (tid & 15) * 8;
    float ad = g_ad1[n * H1C + h];
    float acc[8] = {};
    float den = 0.f;
    int e0 = g_rowptr[n], e1 = g_rowptr[n + 1];
    int srcLane = threadIdx.x & 16;   // lane 0 or 16 within warp owns the expf
    for (int e = e0; e < e1; e++) {
        int s = g_esrc[e];
        float w = 0.f;
        if ((tid & 15) == 0) {
            float ev = g_as1[s * H1C + h] + ad;
            ev = ev > 0.f ? ev : 0.2f * ev;
            w = __expf(ev);
        }
        w = __shfl_sync(0xffffffffu, w, srcLane, 32);
        den += w;
        const float4* hp = (const float4*)(g_h1 + (size_t)s * D1 + c0);
        float4 p = hp[0], q = hp[1];
        acc[0] += w * p.x; acc[1] += w * p.y; acc[2] += w * p.z; acc[3] += w * p.w;
        acc[4] += w * q.x; acc[5] += w * q.y; acc[6] += w * q.z; acc[7] += w * q.w;
    }
    float inv = 1.f / (den + 1e-16f);
    __nv_bfloat16 hv[8], lv[8];
#pragma unroll
    for (int j = 0; j < 8; j++) {
        float v = acc[j] * inv + b1[c0 + j];
        v = v > 0.f ? v : expm1f(v);
        __nv_bfloat16 hb = __float2bfloat16(v);
        hv[j] = hb;
        lv[j] = __float2bfloat16(v - __bfloat162float(hb));
    }
    size_t off = (size_t)n * D1 + c0;
    *(uint4*)(g_acth + off) = *(uint4*)hv;
    *(uint4*)(g_actl + off) = *(uint4*)lv;
}

// ---------------- alpha2: warp per node ----------------
__global__ void k_alpha2(const float* __restrict__ a2s, const float* __restrict__ a2d) {
    int n = (blockIdx.x * blockDim.x + threadIdx.x) >> 5;
    int lane = threadIdx.x & 31;
    if (n >= NN) return;
    size_t base = (size_t)n * OUTC;
    float z0 = g_z[base + lane];
    float z1 = g_z[base + lane + 32];
    float s = z0 * a2s[lane] + z1 * a2s[lane + 32];
    float d = z0 * a2d[lane] + z1 * a2d[lane + 32];
    for (int o = 16; o; o >>= 1) {
        s += __shfl_down_sync(0xffffffffu, s, o);
        d += __shfl_down_sync(0xffffffffu, d, o);
    }
    if (lane == 0) { g_as2[n] = s; g_ad2[n] = d; }
}

// ---------------- CSR edge pass 2: warp per dst node, fused final output ----------------
__global__ void k_edge2(float* __restrict__ out, const float* __restrict__ b2) {
    int n = (blockIdx.x * blockDim.x + threadIdx.x) >> 5;
    int lane = threadIdx.x & 31;
    if (n >= NN) return;
    float ad = g_ad2[n];
    float acc0 = 0.f, acc1 = 0.f, den = 0.f;
    int e0 = g_rowptr[n], e1 = g_rowptr[n + 1];
    for (int e = e0; e < e1; e++) {
        int s = g_esrc[e];
        float w = 0.f;
        if (lane == 0) {
            float ev = g_as2[s] + ad;
            ev = ev > 0.f ? ev : 0.2f * ev;
            w = __expf(ev);
        }
        w = __shfl_sync(0xffffffffu, w, 0, 32);
        den += w;
        const float* zs = g_z + (size_t)s * OUTC;
        acc0 += w * zs[lane];
        acc1 += w * zs[lane + 32];
    }
    float inv = 1.f / (den + 1e-16f);
    out[(size_t)n * OUTC + lane]      = acc0 * inv + b2[lane];
    out[(size_t)n * OUTC + lane + 32] = acc1 * inv + b2[lane + 32];
}

// ---------------- host launcher ----------------
extern "C" void kernel_launch(void* const* d_in, const int* in_sizes, int n_in,
                              void* d_out, int out_size) {
    const float* x    = (const float*)d_in[0];
    const void*  ei   = d_in[1];
    const float* W1   = (const float*)d_in[2];
    const float* a_s1 = (const float*)d_in[3];
    const float* a_d1 = (const float*)d_in[4];
    const float* b1   = (const float*)d_in[5];
    const float* W2   = (const float*)d_in[6];
    const float* a_s2 = (const float*)d_in[7];
    const float* a_d2 = (const float*)d_in[8];
    const float* b2   = (const float*)d_in[9];
    float* out = (float*)d_out;

    int E = in_sizes[1] / 2;
    if (E > MAXE) E = MAXE;
    int EE = E + NN;

    // CSR build + operand conversion
    k_prep<<<(NN + 255) / 256, 256>>>((const int*)ei, E);
    k_build_hist<<<(EE + 255) / 256, 256>>>(ei, E, EE);
    k_scan<<<1, 1024>>>();
    k_scatter<<<(EE + 255) / 256, 256>>>(EE);
    {
        int total = NN * INC + D1 * INC + OUTC * D1;
        k_cvt<<<(total + 255) / 256, 256>>>(x, W1, W2);
    }

    // layer 1
    k_gemm1<<<dim3(D1 / 128, (NN + 127) / 128), 256>>>();
    k_alpha1<<<(NN * H1C * 32 + 255) / 256, 256>>>(a_s1, a_d1);
    k_edge1<<<NN, 128>>>(b1);

    // layer 2
    k_gemm2<<<(NN + 127) / 128, 256>>>();
    k_alpha2<<<(NN * 32 + 255) / 256, 256>>>(a_s2, a_d2);
    k_edge2<<<(NN * 32 + 255) / 256, 256>>>(out, b2);
}

// round 15
// speedup vs baseline: 1.2811x; 1.0507x over previous
#include <cuda_runtime.h>
#include <cuda_bf16.h>
#include <cstdint>
#include <math.h>

// Problem constants (fixed shapes per reference)
#define NN    10000
#define INC   128
#define H1C   8
#define C1C   128
#define D1    1024      // H1C*C1C
#define OUTC  64
#define MAXE  200000
#define MAXEE (MAXE + NN)

// ---------------- warp-level MMA helpers (baseline sm_80+ ISA; no 'a' features) ----------------
__device__ __forceinline__ uint32_t smem_to_u32(const void* p) {
    uint32_t a;
    asm("{ .reg .u64 t; cvta.to.shared.u64 t, %1; cvt.u32.u64 %0, t; }" : "=r"(a) : "l"(p));
    return a;
}
__device__ __forceinline__ void ldmx4(uint32_t addr, uint32_t& r0, uint32_t& r1,
                                      uint32_t& r2, uint32_t& r3) {
    asm volatile("ldmatrix.sync.aligned.m8n8.x4.shared.b16 {%0,%1,%2,%3}, [%4];"
        : "=r"(r0), "=r"(r1), "=r"(r2), "=r"(r3) : "r"(addr));
}
__device__ __forceinline__ void mma16816(float* c, const uint32_t* a, const uint32_t* b) {
    asm volatile("mma.sync.aligned.m16n8k16.row.col.f32.bf16.bf16.f32 "
        "{%0,%1,%2,%3}, {%4,%5,%6,%7}, {%8,%9}, {%0,%1,%2,%3};"
        : "+f"(c[0]), "+f"(c[1]), "+f"(c[2]), "+f"(c[3])
        : "r"(a[0]), "r"(a[1]), "r"(a[2]), "r"(a[3]), "r"(b[0]), "r"(b[1]));
}
// reduce over the 4 lanes of a quad (lanes sharing lane>>2)
__device__ __forceinline__ float quad_red(float v) {
    v += __shfl_down_sync(0xffffffffu, v, 1, 4);
    v += __shfl_down_sync(0xffffffffu, v, 2, 4);
    return v;
}

// ---------------- device scratch (no allocations allowed) ----------------
__device__ int   g_src[MAXEE];
__device__ int   g_dst[MAXEE];
__device__ int   g_esrc[MAXEE];     // CSR: src per dst-sorted edge
__device__ int   g_rowptr[NN + 1];
__device__ int   g_cursor[NN];
__device__ int   g_deg[NN];
__device__ float g_h1[NN * D1];     // gemm1 output (fp32)
__device__ float g_as1[NN * H1C];
__device__ float g_ad1[NN * H1C];
__device__ float g_z[NN * OUTC];
__device__ float g_as2[NN];
__device__ float g_ad2[NN];
__device__ int   g_is64;
// split-bf16 operands
__device__ __nv_bfloat16 g_xh[NN * INC];
__device__ __nv_bfloat16 g_xl[NN * INC];
__device__ __nv_bfloat16 g_w1th[D1 * INC];   // W1^T hi  [n][k]
__device__ __nv_bfloat16 g_w1tl[D1 * INC];   // W1^T lo
__device__ __nv_bfloat16 g_w2th[OUTC * D1];  // W2^T hi
__device__ __nv_bfloat16 g_w2tl[OUTC * D1];  // W2^T lo
__device__ __nv_bfloat16 g_acth[NN * D1];    // layer-1 activation hi
__device__ __nv_bfloat16 g_actl[NN * D1];    // layer-1 activation lo

// ---------------- prep: zero degree array; block 0 also detects edge dtype ----------------
__global__ void k_prep(const int* __restrict__ ei, int E) {
    int i = blockIdx.x * blockDim.x + threadIdx.x;
    if (i < NN) g_deg[i] = 0;
    if (blockIdx.x == 0) {
        __shared__ int nz;
        if (threadIdx.x == 0) nz = 0;
        __syncthreads();
        int n = E < 1000 ? E : 1000;
        int local = 0;
        for (int j = threadIdx.x; j < n; j += blockDim.x)
            if (ei[2 * j + 1] != 0) local = 1;
        if (local) atomicOr(&nz, 1);
        __syncthreads();
        if (threadIdx.x == 0) g_is64 = (nz == 0) ? 1 : 0;
    }
}

// Build int32 src/dst with self-loops appended + histogram of dst degrees. 4 edges/thread.
__global__ void k_build_hist(const void* __restrict__ ei, int E, int total) {
    int i0 = (blockIdx.x * blockDim.x + threadIdx.x) * 4;
#pragma unroll
    for (int j = 0; j < 4; j++) {
        int i = i0 + j;
        if (i >= total) return;
        int s, d;
        if (i < E) {
            if (g_is64) {
                const long long* p = (const long long*)ei;
                s = (int)p[i];
                d = (int)p[E + i];
            } else {
                const int* p = (const int*)ei;
                s = p[i];
                d = p[E + i];
            }
        } else {
            s = i - E;
            d = i - E;
        }
        s = s < 0 ? 0 : (s >= NN ? NN - 1 : s);
        d = d < 0 ? 0 : (d >= NN ? NN - 1 : d);
        g_src[i] = s;
        g_dst[i] = d;
        atomicAdd(&g_deg[d], 1);
    }
}

// Exclusive scan of g_deg -> g_rowptr (and init g_cursor). Single block, 1024 threads.
__global__ void k_scan() {
    __shared__ int sums[1024];
    const int CH = (NN + 1023) / 1024;   // 10
    int tid = threadIdx.x;
    int base = tid * CH;
    int s = 0;
    for (int j = 0; j < CH; j++) {
        int idx = base + j;
        if (idx < NN) s += g_deg[idx];
    }
    sums[tid] = s;
    __syncthreads();
    for (int off = 1; off < 1024; off <<= 1) {
        int v = (tid >= off) ? sums[tid - off] : 0;
        __syncthreads();
        sums[tid] += v;
        __syncthreads();
    }
    int run = (tid == 0) ? 0 : sums[tid - 1];
    for (int j = 0; j < CH; j++) {
        int idx = base + j;
        if (idx < NN) {
            g_rowptr[idx] = run;
            g_cursor[idx] = run;
            run += g_deg[idx];
        }
    }
    if (tid == 1023) g_rowptr[NN] = run;
}

// 4 edges/thread for atomic MLP
__global__ void k_scatter(int EE) {
    int i0 = (blockIdx.x * blockDim.x + threadIdx.x) * 4;
#pragma unroll
    for (int j = 0; j < 4; j++) {
        int i = i0 + j;
        if (i >= EE) return;
        int p = atomicAdd(&g_cursor[g_dst[i]], 1);
        g_esrc[p] = g_src[i];
    }
}

// ---------------- split-bf16 conversion: x, W1^T, W2^T ----------------
__global__ void k_cvt(const float* __restrict__ x, const float* __restrict__ W1,
                      const float* __restrict__ W2) {
    const int NX = NN * INC;           // 1,280,000
    const int NW1 = D1 * INC;          // 131,072
    const int NW2 = OUTC * D1;         // 65,536
    int i = blockIdx.x * blockDim.x + threadIdx.x;
    if (i < NX) {
        float v = x[i];
        __nv_bfloat16 h = __float2bfloat16(v);
        g_xh[i] = h;
        g_xl[i] = __float2bfloat16(v - __bfloat162float(h));
    } else if (i < NX + NW1) {
        int idx = i - NX;
        int n = idx >> 7, k = idx & 127;           // [n][k] <- W1[k][n]
        float v = W1[(size_t)k * D1 + n];
        __nv_bfloat16 h = __float2bfloat16(v);
        g_w1th[idx] = h;
        g_w1tl[idx] = __float2bfloat16(v - __bfloat162float(h));
    } else if (i < NX + NW1 + NW2) {
        int idx = i - NX - NW1;
        int n = idx >> 10, k = idx & 1023;         // [n][k] <- W2[k][n]
        float v = W2[(size_t)k * OUTC + n];
        __nv_bfloat16 h = __float2bfloat16(v);
        g_w2th[idx] = h;
        g_w2tl[idx] = __float2bfloat16(v - __bfloat162float(h));
    }
}

// smem row pitch: 72 bf16 = 144 bytes = 9 x 16B => ldmatrix conflict-free, no swizzle
#define PITCH 72

// ---------------- GEMM1 (HMMA): g_h1 = x @ W1 via concatenated-K split-bf16 ----------------
// K' = 384 (xh@Wh | xh@Wl | xl@Wh), 6 chunks of 64. CTA tile 128x128, 8 warps of 32x64.
// Fused epilogue: per-head alpha_src/alpha_dst (tile's 128 N-cols == head blockIdx.x).
__global__ void __launch_bounds__(256) k_gemm1(const float* __restrict__ asrc,
                                               const float* __restrict__ adst) {
    __shared__ __align__(16) __nv_bfloat16 smA[128 * PITCH];
    __shared__ __align__(16) __nv_bfloat16 smB[128 * PITCH];
    __shared__ float sredS[2][128];
    __shared__ float sredD[2][128];
    int tid = threadIdx.x, wid = tid >> 5, lane = tid & 31;
    int row0 = blockIdx.y * 128, col0 = blockIdx.x * 128;
    int mw = (wid >> 1) * 32, nw = (wid & 1) * 64;
    float acc[2][8][4];
#pragma unroll
    for (int mi = 0; mi < 2; mi++)
#pragma unroll
        for (int ni = 0; ni < 8; ni++)
#pragma unroll
            for (int j = 0; j < 4; j++) acc[mi][ni][j] = 0.f;

    uint32_t smA32 = smem_to_u32(smA), smB32 = smem_to_u32(smB);
    uint32_t aAddr = smA32 + (mw + (lane & 15)) * 144 + (lane >> 4) * 16;
    uint32_t bAddr = smB32 + (nw + (lane & 7) + ((lane >> 4) & 1) * 8) * 144 + ((lane >> 3) & 1) * 16;

    for (int ci = 0; ci < 6; ci++) {
        int t = ci >> 1, kin = (ci & 1) * 64;
        const __nv_bfloat16* Ag = (t < 2) ? g_xh : g_xl;
        const __nv_bfloat16* Bg = (t == 1) ? g_w1tl : g_w1th;
#pragma unroll
        for (int i = 0; i < 4; i++) {
            int u = tid + i * 256;
            int r = u >> 3, q = u & 7;
            int gm = row0 + r;
            uint4 v = make_uint4(0u, 0u, 0u, 0u);
            if (gm < NN) v = *(const uint4*)(Ag + (size_t)gm * INC + kin + q * 8);
            *(uint4*)(smA + r * PITCH + q * 8) = v;
        }
#pragma unroll
        for (int i = 0; i < 4; i++) {
            int u = tid + i * 256;
            int r = u >> 3, q = u & 7;
            int gn = col0 + r;
            uint4 v = make_uint4(0u, 0u, 0u, 0u);
            if (gn < D1) v = *(const uint4*)(Bg + (size_t)gn * INC + kin + q * 8);
            *(uint4*)(smB + r * PITCH + q * 8) = v;
        }
        __syncthreads();
#pragma unroll
        for (int kk = 0; kk < 4; kk++) {
            uint32_t a[2][4], b[8][2];
            ldmx4(aAddr + kk * 32, a[0][0], a[0][1], a[0][2], a[0][3]);
            ldmx4(aAddr + 16 * 144 + kk * 32, a[1][0], a[1][1], a[1][2], a[1][3]);
#pragma unroll
            for (int nt = 0; nt < 4; nt++) {
                uint32_t r0, r1, r2, r3;
                ldmx4(bAddr + nt * 16 * 144 + kk * 32, r0, r1, r2, r3);
                b[nt * 2][0] = r0; b[nt * 2][1] = r1;
                b[nt * 2 + 1][0] = r2; b[nt * 2 + 1][1] = r3;
            }
#pragma unroll
            for (int mi = 0; mi < 2; mi++)
#pragma unroll
                for (int ni = 0; ni < 8; ni++)
                    mma16816(acc[mi][ni], a[mi], b[ni]);
        }
        __syncthreads();
    }

    // epilogue: write fp32 h1
    int rbase = row0 + mw + (lane >> 2);
    int cbase = col0 + nw + (lane & 3) * 2;
#pragma unroll
    for (int mi = 0; mi < 2; mi++)
#pragma unroll
        for (int ni = 0; ni < 8; ni++) {
            int r = rbase + mi * 16;
            int c = cbase + ni * 8;
            if (r < NN)
                *(float2*)(g_h1 + (size_t)r * D1 + c) = make_float2(acc[mi][ni][0], acc[mi][ni][1]);
            if (r + 8 < NN)
                *(float2*)(g_h1 + (size_t)(r + 8) * D1 + c) = make_float2(acc[mi][ni][2], acc[mi][ni][3]);
        }

    // fused alpha1: head h = blockIdx.x; per-row dot with a_src/a_dst over 128 cols.
    int h = blockIdx.x;
    {
        float ps[2][2] = {}, pd[2][2] = {};   // [mi][row-half (j01 vs j23)]
#pragma unroll
        for (int ni = 0; ni < 8; ni++) {
            int c = nw + ni * 8 + (lane & 3) * 2;
            float s0 = __ldg(asrc + h * C1C + c), s1 = __ldg(asrc + h * C1C + c + 1);
            float d0 = __ldg(adst + h * C1C + c), d1 = __ldg(adst + h * C1C + c + 1);
#pragma unroll
            for (int mi = 0; mi < 2; mi++) {
                ps[mi][0] += acc[mi][ni][0] * s0 + acc[mi][ni][1] * s1;
                ps[mi][1] += acc[mi][ni][2] * s0 + acc[mi][ni][3] * s1;
                pd[mi][0] += acc[mi][ni][0] * d0 + acc[mi][ni][1] * d1;
                pd[mi][1] += acc[mi][ni][2] * d0 + acc[mi][ni][3] * d1;
            }
        }
#pragma unroll
        for (int mi = 0; mi < 2; mi++) {
            ps[mi][0] = quad_red(ps[mi][0]); ps[mi][1] = quad_red(ps[mi][1]);
            pd[mi][0] = quad_red(pd[mi][0]); pd[mi][1] = quad_red(pd[mi][1]);
        }
        if ((lane & 3) == 0) {
            int rloc = mw + (lane >> 2);
#pragma unroll
            for (int mi = 0; mi < 2; mi++) {
                sredS[wid & 1][rloc + mi * 16]     = ps[mi][0];
                sredS[wid & 1][rloc + mi * 16 + 8] = ps[mi][1];
                sredD[wid & 1][rloc + mi * 16]     = pd[mi][0];
                sredD[wid & 1][rloc + mi * 16 + 8] = pd[mi][1];
            }
        }
        __syncthreads();
        if (tid < 128) {
            int r = row0 + tid;
            if (r < NN) {
                g_as1[r * H1C + h] = sredS[0][tid] + sredS[1][tid];
                g_ad1[r * H1C + h] = sredD[0][tid] + sredD[1][tid];
            }
        }
    }
}

// ---------------- GEMM2 (HMMA): g_z = act @ W2 via concatenated-K split-bf16 ----------------
// K' = 3072 (48 chunks of 64). CTA tile 128x64, 8 warps of 16x64.
// Fused epilogue: alpha2 (warp tile covers all 64 cols -> intra-warp quad reduction).
__global__ void __launch_bounds__(256) k_gemm2(const float* __restrict__ a2s,
                                               const float* __restrict__ a2d) {
    __shared__ __align__(16) __nv_bfloat16 smA[128 * PITCH];
    __shared__ __align__(16) __nv_bfloat16 smB[64 * PITCH];
    int tid = threadIdx.x, wid = tid >> 5, lane = tid & 31;
    int row0 = blockIdx.x * 128;
    int mw = wid * 16;
    float acc[8][4];
#pragma unroll
    for (int ni = 0; ni < 8; ni++)
#pragma unroll
        for (int j = 0; j < 4; j++) acc[ni][j] = 0.f;

    uint32_t smA32 = smem_to_u32(smA), smB32 = smem_to_u32(smB);
    uint32_t aAddr = smA32 + (mw + (lane & 15)) * 144 + (lane >> 4) * 16;
    uint32_t bAddr = smB32 + ((lane & 7) + ((lane >> 4) & 1) * 8) * 144 + ((lane >> 3) & 1) * 16;

    for (int ci = 0; ci < 48; ci++) {
        int t = ci >> 4, kin = (ci & 15) * 64;
        const __nv_bfloat16* Ag = (t < 2) ? g_acth : g_actl;
        const __nv_bfloat16* Bg = (t == 1) ? g_w2tl : g_w2th;
#pragma unroll
        for (int i = 0; i < 4; i++) {
            int u = tid + i * 256;
            int r = u >> 3, q = u & 7;
            int gm = row0 + r;
            uint4 v = make_uint4(0u, 0u, 0u, 0u);
            if (gm < NN) v = *(const uint4*)(Ag + (size_t)gm * D1 + kin + q * 8);
            *(uint4*)(smA + r * PITCH + q * 8) = v;
        }
#pragma unroll
        for (int i = 0; i < 2; i++) {
            int u = tid + i * 256;
            int r = u >> 3, q = u & 7;
            uint4 v = *(const uint4*)(Bg + (size_t)r * D1 + kin + q * 8);
            *(uint4*)(smB + r * PITCH + q * 8) = v;
        }
        __syncthreads();
#pragma unroll
        for (int kk = 0; kk < 4; kk++) {
            uint32_t a[4], b[8][2];
            ldmx4(aAddr + kk * 32, a[0], a[1], a[2], a[3]);
#pragma unroll
            for (int nt = 0; nt < 4; nt++) {
                uint32_t r0, r1, r2, r3;
                ldmx4(bAddr + nt * 16 * 144 + kk * 32, r0, r1, r2, r3);
                b[nt * 2][0] = r0; b[nt * 2][1] = r1;
                b[nt * 2 + 1][0] = r2; b[nt * 2 + 1][1] = r3;
            }
#pragma unroll
            for (int ni = 0; ni < 8; ni++)
                mma16816(acc[ni], a, b[ni]);
        }
        __syncthreads();
    }
    int rbase = row0 + mw + (lane >> 2);
    int cbase = (lane & 3) * 2;
#pragma unroll
    for (int ni = 0; ni < 8; ni++) {
        int c = cbase + ni * 8;
        if (rbase < NN)
            *(float2*)(g_z + (size_t)rbase * OUTC + c) = make_float2(acc[ni][0], acc[ni][1]);
        if (rbase + 8 < NN)
            *(float2*)(g_z + (size_t)(rbase + 8) * OUTC + c) = make_float2(acc[ni][2], acc[ni][3]);
    }

    // fused alpha2
    {
        float ps0 = 0.f, ps1 = 0.f, pd0 = 0.f, pd1 = 0.f;
#pragma unroll
        for (int ni = 0; ni < 8; ni++) {
            int c = cbase + ni * 8;
            float s0 = __ldg(a2s + c), s1 = __ldg(a2s + c + 1);
            float d0 = __ldg(a2d + c), d1 = __ldg(a2d + c + 1);
            ps0 += acc[ni][0] * s0 + acc[ni][1] * s1;
            ps1 += acc[ni][2] * s0 + acc[ni][3] * s1;
            pd0 += acc[ni][0] * d0 + acc[ni][1] * d1;
            pd1 += acc[ni][2] * d0 + acc[ni][3] * d1;
        }
        ps0 = quad_red(ps0); ps1 = quad_red(ps1);
        pd0 = quad_red(pd0); pd1 = quad_red(pd1);
        if ((lane & 3) == 0) {
            if (rbase < NN)     { g_as2[rbase] = ps0;     g_ad2[rbase] = pd0; }
            if (rbase + 8 < NN) { g_as2[rbase + 8] = ps1; g_ad2[rbase + 8] = pd1; }
        }
    }
}

// ---------------- CSR edge pass 1: block per dst node, fused softmax+agg+elu ----------------
// Output written directly as split-bf16 (hi/lo) for GEMM2.
__global__ void k_edge1(const float* __restrict__ b1) {
    int n = blockIdx.x;
    int tid = threadIdx.x;
    int h = tid >> 4;
    int c0 = h * C1C + (tid & 15) * 8;
    float ad = g_ad1[n * H1C + h];
    float acc[8] = {};
    float den = 0.f;
    int e0 = g_rowptr[n], e1 = g_rowptr[n + 1];
    int srcLane = threadIdx.x & 16;   // lane 0 or 16 within warp owns the expf
    for (int e = e0; e < e1; e++) {
        int s = g_esrc[e];
        float w = 0.f;
        if ((tid & 15) == 0) {
            float ev = g_as1[s * H1C + h] + ad;
            ev = ev > 0.f ? ev : 0.2f * ev;
            w = __expf(ev);
        }
        w = __shfl_sync(0xffffffffu, w, srcLane, 32);
        den += w;
        const float4* hp = (const float4*)(g_h1 + (size_t)s * D1 + c0);
        float4 p = hp[0], q = hp[1];
        acc[0] += w * p.x; acc[1] += w * p.y; acc[2] += w * p.z; acc[3] += w * p.w;
        acc[4] += w * q.x; acc[5] += w * q.y; acc[6] += w * q.z; acc[7] += w * q.w;
    }
    float inv = 1.f / (den + 1e-16f);
    __nv_bfloat16 hv[8], lv[8];
#pragma unroll
    for (int j = 0; j < 8; j++) {
        float v = acc[j] * inv + b1[c0 + j];
        v = v > 0.f ? v : expm1f(v);
        __nv_bfloat16 hb = __float2bfloat16(v);
        hv[j] = hb;
        lv[j] = __float2bfloat16(v - __bfloat162float(hb));
    }
    size_t off = (size_t)n * D1 + c0;
    *(uint4*)(g_acth + off) = *(uint4*)hv;
    *(uint4*)(g_actl + off) = *(uint4*)lv;
}

// ---------------- CSR edge pass 2: warp per dst node, fused final output ----------------
__global__ void k_edge2(float* __restrict__ out, const float* __restrict__ b2) {
    int n = (blockIdx.x * blockDim.x + threadIdx.x) >> 5;
    int lane = threadIdx.x & 31;
    if (n >= NN) return;
    float ad = g_ad2[n];
    float acc0 = 0.f, acc1 = 0.f, den = 0.f;
    int e0 = g_rowptr[n], e1 = g_rowptr[n + 1];
    for (int e = e0; e < e1; e++) {
        int s = g_esrc[e];
        float w = 0.f;
        if (lane == 0) {
            float ev = g_as2[s] + ad;
            ev = ev > 0.f ? ev : 0.2f * ev;
            w = __expf(ev);
        }
        w = __shfl_sync(0xffffffffu, w, 0, 32);
        den += w;
        const float* zs = g_z + (size_t)s * OUTC;
        acc0 += w * zs[lane];
        acc1 += w * zs[lane + 32];
    }
    float inv = 1.f / (den + 1e-16f);
    out[(size_t)n * OUTC + lane]      = acc0 * inv + b2[lane];
    out[(size_t)n * OUTC + lane + 32] = acc1 * inv + b2[lane + 32];
}

// ---------------- host launcher ----------------
extern "C" void kernel_launch(void* const* d_in, const int* in_sizes, int n_in,
                              void* d_out, int out_size) {
    const float* x    = (const float*)d_in[0];
    const void*  ei   = d_in[1];
    const float* W1   = (const float*)d_in[2];
    const float* a_s1 = (const float*)d_in[3];
    const float* a_d1 = (const float*)d_in[4];
    const float* b1   = (const float*)d_in[5];
    const float* W2   = (const float*)d_in[6];
    const float* a_s2 = (const float*)d_in[7];
    const float* a_d2 = (const float*)d_in[8];
    const float* b2   = (const float*)d_in[9];
    float* out = (float*)d_out;

    int E = in_sizes[1] / 2;
    if (E > MAXE) E = MAXE;
    int EE = E + NN;

    // CSR build + operand conversion
    k_prep<<<(NN + 255) / 256, 256>>>((const int*)ei, E);
    k_build_hist<<<(EE + 1023) / 1024, 256>>>(ei, E, EE);
    k_scan<<<1, 1024>>>();
    k_scatter<<<(EE + 1023) / 1024, 256>>>(EE);
    {
        int total = NN * INC + D1 * INC + OUTC * D1;
        k_cvt<<<(total + 255) / 256, 256>>>(x, W1, W2);
    }

    // layer 1 (alpha1 fused into gemm1 epilogue)
    k_gemm1<<<dim3(D1 / 128, (NN + 127) / 128), 256>>>(a_s1, a_d1);
    k_edge1<<<NN, 128>>>(b1);

    // layer 2 (alpha2 fused into gemm2 epilogue)
    k_gemm2<<<(NN + 127) / 128, 256>>>(a_s2, a_d2);
    k_edge2<<<(NN * 32 + 255) / 256, 256>>>(out, b2);
}